// round 5
// baseline (speedup 1.0000x reference)
#include <cuda_runtime.h>
#include <cuda_bf16.h>
#include <cstdint>

// Problem constants
#define B_    8
#define L_    2048
#define D_    64
#define TOPK_ 32

// Fused tiling
#define TQ     32                // query rows per block
#define CK     128               // keys per chunk
#define NCHUNK (L_ / CK)         // 16
#define NBLK   (B_ * L_ / TQ)    // 512 blocks
#define BPB    (L_ / TQ)         // 64 blocks per batch

// Selection
#define MINC 48                  // min candidates (bf16 rank-margin safety)
#define CAP  128                 // candidate cap per row

// ---- dynamic shared memory layout (bytes) ----
// [0,            131072)  Ssc  : u16 [32][2048] sortable-bf16 scores
// [131072,       200704)  Ks   : float [2][128][68] K double buffer
//      overlay (selection phase, after GEMM done):
//        cand_idx int[32][128]   @ 131072      (16384)
//        cand_val double[32][128]@ 147456      (32768)
//        sel_idx  int[32][32]    @ 180224      (4096)
//        sel_val  float[32][32]  @ 184320      (4096)
// [200704,       209408)  Qs   : float [32][68]
#define SMEM_BYTES 209408
#define OFF_SSC   0
#define OFF_KS    131072
#define OFF_CIDX  131072
#define OFF_CVAL  147456
#define OFF_SIDX  180224
#define OFF_SVAL  184320
#define OFF_QS    200704

__device__ __forceinline__ unsigned short f2s16(float f) {
    unsigned short b = __bfloat16_as_ushort(__float2bfloat16(f));
    return (b & 0x8000) ? (unsigned short)~b : (unsigned short)(b | 0x8000);
}

__device__ __forceinline__ void dot2_step(float a, float b, float& s, float& c) {
    float p  = __fmul_rn(a, b);
    float e  = __fmaf_rn(a, b, -p);          // exact product error
    float t1 = __fadd_rn(s, p);              // TwoSum
    float bv = __fsub_rn(t1, s);
    float e2 = __fadd_rn(__fsub_rn(s, __fsub_rn(t1, bv)), __fsub_rn(p, bv));
    s = t1;
    c = __fadd_rn(c, __fadd_rn(e, e2));
}

__device__ __forceinline__ void cp_async16(uint32_t smem_dst, const void* gsrc) {
    asm volatile("cp.async.cg.shared.global [%0], [%1], 16;\n"
                 :: "r"(smem_dst), "l"(gsrc));
}
__device__ __forceinline__ void cp_commit() {
    asm volatile("cp.async.commit_group;\n");
}
template <int N>
__device__ __forceinline__ void cp_wait() {
    asm volatile("cp.async.wait_group %0;\n" :: "n"(N));
}

__global__ __launch_bounds__(256, 1) void fused_topk_attn(
    const float* __restrict__ q, const float* __restrict__ k,
    const float* __restrict__ v, float* __restrict__ out)
{
    extern __shared__ __align__(16) char smem[];
    unsigned short* Ssc = (unsigned short*)(smem + OFF_SSC);
    float*  Ks   = (float*)(smem + OFF_KS);
    float*  Qs   = (float*)(smem + OFF_QS);
    int*    cidx = (int*)(smem + OFF_CIDX);
    double* cval = (double*)(smem + OFF_CVAL);
    int*    sidx = (int*)(smem + OFF_SIDX);
    float*  sval = (float*)(smem + OFF_SVAL);

    const int t    = threadIdx.x;
    const int lane = t & 31;
    const int w    = t >> 5;

    const int rowBase = blockIdx.x * TQ;
    const int b       = blockIdx.x / BPB;
    const float* kb   = k + (size_t)b * L_ * D_;
    const float* vb   = v + (size_t)b * L_ * D_;

    const uint32_t ksBase = (uint32_t)__cvta_generic_to_shared(Ks);

    // ---- stage Q (fp32, padded stride 68) ----
    {
        for (int i = t; i < TQ * 16; i += 256) {
            int row = i >> 4, dg4 = (i & 15) << 2;
            float4 qv = *(const float4*)(q + ((size_t)(rowBase + row)) * D_ + dg4);
            *(float4*)(Qs + row * 68 + dg4) = qv;
        }
    }

    // ---- prologue: async-load K chunk 0 into buffer 0 ----
    {
        for (int i = t; i < CK * 16; i += 256) {
            int row = i >> 4, dg4 = i & 15;
            cp_async16(ksBase + (uint32_t)(row * 272 + dg4 * 16),
                       kb + (size_t)row * D_ + dg4 * 4);
        }
        cp_commit();
    }

    // ---- GEMM mainloop: 4 rows x 4 keys per thread ----
    const int ty = t & 7;          // q-row group: rows ty + 8r
    const int tx = t >> 3;         // key group : keys tx + 32c

    for (int chunk = 0; chunk < NCHUNK; ++chunk) {
        // issue next chunk into the other buffer
        if (chunk + 1 < NCHUNK) {
            const int nb = (chunk + 1) & 1;
            const int keyNext = (chunk + 1) * CK;
            for (int i = t; i < CK * 16; i += 256) {
                int row = i >> 4, dg4 = i & 15;
                cp_async16(ksBase + (uint32_t)(nb * 34816 + row * 272 + dg4 * 16),
                           kb + (size_t)(keyNext + row) * D_ + dg4 * 4);
            }
            cp_commit();
            cp_wait<1>();
        } else {
            cp_wait<0>();
        }
        __syncthreads();

        const float* KsBuf = Ks + (chunk & 1) * (CK * 68);
        float acc[4][4] = {};
        #pragma unroll
        for (int dg = 0; dg < D_; dg += 4) {
            float4 qv[4], kv[4];
            #pragma unroll
            for (int r = 0; r < 4; ++r) qv[r] = *(const float4*)(Qs + (ty + 8 * r) * 68 + dg);
            #pragma unroll
            for (int c = 0; c < 4; ++c) kv[c] = *(const float4*)(KsBuf + (tx + 32 * c) * 68 + dg);
            #pragma unroll
            for (int r = 0; r < 4; ++r)
                #pragma unroll
                for (int c = 0; c < 4; ++c) {
                    acc[r][c] = fmaf(qv[r].x, kv[c].x, acc[r][c]);
                    acc[r][c] = fmaf(qv[r].y, kv[c].y, acc[r][c]);
                    acc[r][c] = fmaf(qv[r].z, kv[c].z, acc[r][c]);
                    acc[r][c] = fmaf(qv[r].w, kv[c].w, acc[r][c]);
                }
        }

        const int keyBase = chunk * CK;
        #pragma unroll
        for (int r = 0; r < 4; ++r)
            #pragma unroll
            for (int c = 0; c < 4; ++c)
                Ssc[(ty + 8 * r) * L_ + keyBase + tx + 32 * c] = f2s16(acc[r][c] * 0.125f);
        __syncthreads();   // protect buffer before it is overwritten next-next iter
    }

    // ---- selection: warp w handles rows 4w .. 4w+3, fully warp-local ----
    const unsigned full = 0xffffffffu;
    const unsigned ltmask = (1u << lane) - 1u;

    for (int rr = 0; rr < 4; ++rr) {
        const int row  = w * 4 + rr;
        const int grow = rowBase + row;
        const uint32_t* row32 = (const uint32_t*)(Ssc + row * L_);
        const float* qrow = Qs + row * 68;

        // q norm -> analytic threshold seed (scores ~ N(0, ||q||^2/64))
        float nx = qrow[lane], ny = qrow[lane + 32];
        float nrm = nx * nx + ny * ny;
        #pragma unroll
        for (int o = 16; o >= 1; o >>= 1) nrm += __shfl_xor_sync(full, nrm, o);

        unsigned mid = f2s16(1.95f * sqrtf(nrm) * 0.125f);
        unsigned lo = 0u, hi = 65536u, tau = 0u;
        bool have = false;
        for (int it = 0; it < 24; ++it) {
            int cnt = 0;
            #pragma unroll
            for (int j = 0; j < 32; ++j) {
                uint32_t p  = row32[j * 32 + lane];
                cnt += ((p & 0xFFFFu) >= mid) + ((p >> 16) >= mid);
            }
            #pragma unroll
            for (int o = 16; o >= 1; o >>= 1) cnt += __shfl_xor_sync(full, cnt, o);
            if (cnt >= MINC && cnt <= CAP) { tau = mid; have = true; break; }
            if (cnt < MINC) hi = mid; else { lo = mid; tau = mid; have = true; }
            mid = lo + ((hi - lo) >> 1);
            if (mid == lo) { if (!have) tau = lo; break; }
        }

        // ballot compaction of candidates
        int* ci = cidx + row * CAP;
        int base = 0;
        #pragma unroll
        for (int j = 0; j < 32; ++j) {
            uint32_t p = row32[j * 32 + lane];
            bool c0 = (p & 0xFFFFu) >= tau;
            bool c1 = (p >> 16) >= tau;
            unsigned m0 = __ballot_sync(full, c0);
            unsigned m1 = __ballot_sync(full, c1);
            if (c0) {
                int pos = base + __popc(m0 & ltmask);
                if (pos < CAP) ci[pos] = (j * 32 + lane) * 2;
            }
            base += __popc(m0);
            if (c1) {
                int pos = base + __popc(m1 & ltmask);
                if (pos < CAP) ci[pos] = (j * 32 + lane) * 2 + 1;
            }
            base += __popc(m1);
        }
        int n = base < CAP ? base : CAP;
        __syncwarp();

        // refine candidates with compensated fp32 dot (matches fp64 ordering)
        double* cv = cval + row * CAP;
        for (int i = lane; i < n; i += 32) {
            const float4* k4 = (const float4*)(kb + (size_t)ci[i] * D_);
            const float4* q4 = (const float4*)qrow;
            float s = 0.0f, c = 0.0f;
            #pragma unroll
            for (int dg = 0; dg < D_ / 4; ++dg) {
                float4 kv = k4[dg];
                float4 qv = q4[dg];
                dot2_step(qv.x, kv.x, s, c);
                dot2_step(qv.y, kv.y, s, c);
                dot2_step(qv.z, kv.z, s, c);
                dot2_step(qv.w, kv.w, s, c);
            }
            cv[i] = ((double)s + (double)c) * 0.125;
        }
        __syncwarp();

        // parallel rank -> exact top-32 (val desc, tie -> lower index)
        int* si = sidx + row * TOPK_;
        float* sv = sval + row * TOPK_;
        for (int i = lane; i < n; i += 32) {
            double vi = cv[i];
            int    ii = ci[i];
            int rank = 0;
            for (int j = 0; j < n; ++j) {
                double vj = cv[j];
                rank += (vj > vi) || (vj == vi && ci[j] < ii);
            }
            if (rank < TOPK_) { si[rank] = ii; sv[rank] = (float)vi; }
        }
        __syncwarp();

        // output: out[grow][d] = sum_j val_j * V[idx_j][d]
        float a0 = 0.0f, a1 = 0.0f;
        #pragma unroll
        for (int j = 0; j < TOPK_; ++j) {
            float vv = sv[j];
            const float* vrow = vb + (size_t)si[j] * D_;
            a0 = fmaf(vv, vrow[lane], a0);
            a1 = fmaf(vv, vrow[lane + 32], a1);
        }
        out[(size_t)grow * D_ + lane]      = a0;
        out[(size_t)grow * D_ + lane + 32] = a1;
        __syncwarp();
    }
}

// ---------------------------------------------------------------------------
extern "C" void kernel_launch(void* const* d_in, const int* in_sizes, int n_in,
                              void* d_out, int out_size)
{
    const float* q = (const float*)d_in[0];
    const float* k = (const float*)d_in[1];
    const float* v = (const float*)d_in[2];
    float* out = (float*)d_out;

    cudaFuncSetAttribute(fused_topk_attn,
                         cudaFuncAttributeMaxDynamicSharedMemorySize, SMEM_BYTES);
    fused_topk_attn<<<NBLK, 256, SMEM_BYTES>>>(q, k, v, out);
}

// round 7
// speedup vs baseline: 1.5545x; 1.5545x over previous
#include <cuda_runtime.h>
#include <cuda_bf16.h>
#include <cstdint>

// Problem constants
#define B_    8
#define L_    2048
#define D_    64
#define TOPK_ 32

// Fused tiling
#define TQ     32                // query rows per block
#define CK     128               // keys per chunk
#define NCHUNK (L_ / CK)         // 16
#define NBLK   (B_ * L_ / TQ)    // 512
#define BPB    (L_ / TQ)         // 64

// Selection
#define MINC 48                  // min candidates (bf16 rank-margin)
#define CAP  96                  // candidate cap per row

// Strides (elements)
#define QST  72                  // Qbf row stride (bf16)
#define KST  72                  // Kbf row stride (bf16)
#define SROW 2056                // Ssc row stride (u16)

// ---- dynamic shared memory layout (bytes) ----
#define OFF_SSC   0              // u16 [32][2056]            = 131584
#define OFF_KBF   131584         // bf16 [2][128][72]         = 36864
#define OFF_CIDX  131584         //   overlay: int   [32][96] = 12288
#define OFF_CVAL  143872         //   overlay: double[32][96] = 24576
#define OFF_QBF   168448         // bf16 [32][72]             = 4608
#define OFF_QS    173056         // f32  [32][68]             = 8704
#define OFF_SIDX  181760         // int  [32][32]             = 4096
#define OFF_SVAL  185856         // f32  [32][32]             = 4096
#define SMEM_BYTES 189952

__device__ __forceinline__ unsigned short f2s16(float f) {
    unsigned short b = __bfloat16_as_ushort(__float2bfloat16(f));
    return (b & 0x8000) ? (unsigned short)~b : (unsigned short)(b | 0x8000);
}

__device__ __forceinline__ uint32_t pack_bf2(float lo, float hi) {
    __nv_bfloat162 h2 = __floats2bfloat162_rn(lo, hi);
    return *reinterpret_cast<uint32_t*>(&h2);
}

__device__ __forceinline__ void dot2_step(float a, float b, float& s, float& c) {
    float p  = __fmul_rn(a, b);
    float e  = __fmaf_rn(a, b, -p);
    float t1 = __fadd_rn(s, p);
    float bv = __fsub_rn(t1, s);
    float e2 = __fadd_rn(__fsub_rn(s, __fsub_rn(t1, bv)), __fsub_rn(p, bv));
    s = t1;
    c = __fadd_rn(c, __fadd_rn(e, e2));
}

__device__ __forceinline__ void mma_bf16(
    float& c0, float& c1, float& c2, float& c3,
    uint32_t a0, uint32_t a1, uint32_t a2, uint32_t a3,
    uint32_t b0, uint32_t b1)
{
    asm volatile(
        "mma.sync.aligned.m16n8k16.row.col.f32.bf16.bf16.f32 "
        "{%0,%1,%2,%3}, {%4,%5,%6,%7}, {%8,%9}, {%0,%1,%2,%3};\n"
        : "+f"(c0), "+f"(c1), "+f"(c2), "+f"(c3)
        : "r"(a0), "r"(a1), "r"(a2), "r"(a3), "r"(b0), "r"(b1));
}

__global__ __launch_bounds__(256, 1) void fused_topk_attn(
    const float* __restrict__ q, const float* __restrict__ k,
    const float* __restrict__ v, float* __restrict__ out)
{
    extern __shared__ __align__(16) char smem[];
    unsigned short* Ssc = (unsigned short*)(smem + OFF_SSC);
    unsigned short* Kbf = (unsigned short*)(smem + OFF_KBF);
    unsigned short* Qbf = (unsigned short*)(smem + OFF_QBF);
    float*  Qs   = (float*)(smem + OFF_QS);
    int*    cidx = (int*)(smem + OFF_CIDX);
    double* cval = (double*)(smem + OFF_CVAL);
    int*    sidx = (int*)(smem + OFF_SIDX);
    float*  sval = (float*)(smem + OFF_SVAL);

    const int t    = threadIdx.x;
    const int lane = t & 31;
    const int w    = t >> 5;

    const int rowBase = blockIdx.x * TQ;
    const int b       = blockIdx.x / BPB;
    const float* kb   = k + (size_t)b * L_ * D_;
    const float* vb   = v + (size_t)b * L_ * D_;

    // ---- stage Q: fp32 copy (refine) + bf16 copy (mma A operand) ----
    for (int i = t; i < TQ * 16; i += 256) {
        int row = i >> 4, dg4 = (i & 15) << 2;
        float4 qv = *(const float4*)(q + ((size_t)(rowBase + row)) * D_ + dg4);
        *(float4*)(Qs + row * 68 + dg4) = qv;
        *(uint32_t*)&Qbf[row * QST + dg4]     = pack_bf2(qv.x, qv.y);
        *(uint32_t*)&Qbf[row * QST + dg4 + 2] = pack_bf2(qv.z, qv.w);
    }

    // ---- prologue: K chunk 0 -> Kbf buf 0 (fp32 LDG -> bf16 STS) ----
    for (int g = 0; g < 8; ++g) {
        int idx = g * 256 + t;            // 2048 float4 per chunk
        int key = idx >> 4, f4 = idx & 15;
        float4 kv = *(const float4*)(kb + (size_t)key * D_ + f4 * 4);
        *(uint32_t*)&Kbf[key * KST + f4 * 4]     = pack_bf2(kv.x, kv.y);
        *(uint32_t*)&Kbf[key * KST + f4 * 4 + 2] = pack_bf2(kv.z, kv.w);
    }
    __syncthreads();

    // ---- A fragments (Q) loaded ONCE: warp covers rows rg*16..+15 ----
    const int rg = w >> 2;                // row-group (0/1)
    const int ns = w & 3;                 // 32-key slice within chunk
    const int ar = rg * 16 + (lane >> 2);
    const int ac = (lane & 3) * 2;
    uint32_t afr[4][4];
    #pragma unroll
    for (int ks = 0; ks < 4; ++ks) {
        int col = ks * 16 + ac;
        afr[ks][0] = *(uint32_t*)&Qbf[ar * QST + col];
        afr[ks][1] = *(uint32_t*)&Qbf[(ar + 8) * QST + col];
        afr[ks][2] = *(uint32_t*)&Qbf[ar * QST + col + 8];
        afr[ks][3] = *(uint32_t*)&Qbf[(ar + 8) * QST + col + 8];
    }

    // ---- mainloop: HMMA on current buf, pipeline next chunk behind it ----
    for (int chunk = 0; chunk < NCHUNK; ++chunk) {
        float4 nx[8];
        const bool more = (chunk + 1 < NCHUNK);
        if (more) {
            const int keyNext = (chunk + 1) * CK;
            #pragma unroll
            for (int g = 0; g < 8; ++g) {
                int idx = g * 256 + t;
                int key = idx >> 4, f4 = idx & 15;
                nx[g] = *(const float4*)(kb + (size_t)(keyNext + key) * D_ + f4 * 4);
            }
        }

        const unsigned short* Kb = Kbf + (chunk & 1) * (CK * KST);
        const int keyBase = chunk * CK + ns * 32;
        #pragma unroll
        for (int nt = 0; nt < 4; ++nt) {
            // FIX: B operand key index must include the warp's slice offset ns*32
            const int keyInChunk = ns * 32 + nt * 8 + (lane >> 2);
            float c0 = 0.f, c1 = 0.f, c2 = 0.f, c3 = 0.f;
            #pragma unroll
            for (int ks = 0; ks < 4; ++ks) {
                int col = ks * 16 + ac;
                uint32_t b0 = *(const uint32_t*)&Kb[keyInChunk * KST + col];
                uint32_t b1 = *(const uint32_t*)&Kb[keyInChunk * KST + col + 8];
                mma_bf16(c0, c1, c2, c3,
                         afr[ks][0], afr[ks][1], afr[ks][2], afr[ks][3], b0, b1);
            }
            const int scol = keyBase + nt * 8 + ac;
            *(uint32_t*)&Ssc[ar * SROW + scol] =
                (uint32_t)f2s16(c0 * 0.125f) | ((uint32_t)f2s16(c1 * 0.125f) << 16);
            *(uint32_t*)&Ssc[(ar + 8) * SROW + scol] =
                (uint32_t)f2s16(c2 * 0.125f) | ((uint32_t)f2s16(c3 * 0.125f) << 16);
        }

        if (more) {
            unsigned short* Kn = Kbf + ((chunk + 1) & 1) * (CK * KST);
            #pragma unroll
            for (int g = 0; g < 8; ++g) {
                int idx = g * 256 + t;
                int key = idx >> 4, f4 = idx & 15;
                *(uint32_t*)&Kn[key * KST + f4 * 4]     = pack_bf2(nx[g].x, nx[g].y);
                *(uint32_t*)&Kn[key * KST + f4 * 4 + 2] = pack_bf2(nx[g].z, nx[g].w);
            }
        }
        __syncthreads();
    }

    // ---- selection: warp w handles rows 4w..4w+3, warp-local ----
    const unsigned full = 0xffffffffu;
    const unsigned ltmask = (1u << lane) - 1u;

    for (int rr = 0; rr < 4; ++rr) {
        const int row  = w * 4 + rr;
        const int grow = rowBase + row;
        const uint32_t* row32 = (const uint32_t*)(Ssc + row * SROW);
        const float* qrow = Qs + row * 68;

        // analytic threshold seed from ||q|| (scores ~ N(0, ||q||^2/64))
        float nxv = qrow[lane], nyv = qrow[lane + 32];
        float nrm = nxv * nxv + nyv * nyv;
        #pragma unroll
        for (int o = 16; o >= 1; o >>= 1) nrm += __shfl_xor_sync(full, nrm, o);

        unsigned mid = f2s16(1.95f * sqrtf(nrm) * 0.125f);
        unsigned lo = 0u, hi = 65536u, tau = 0u;
        bool have = false;
        for (int it = 0; it < 24; ++it) {
            int cnt = 0;
            #pragma unroll
            for (int j = 0; j < 32; ++j) {
                uint32_t p = row32[j * 32 + lane];
                cnt += ((p & 0xFFFFu) >= mid) + ((p >> 16) >= mid);
            }
            #pragma unroll
            for (int o = 16; o >= 1; o >>= 1) cnt += __shfl_xor_sync(full, cnt, o);
            if (cnt >= MINC && cnt <= CAP) { tau = mid; have = true; break; }
            if (cnt < MINC) hi = mid; else { lo = mid; tau = mid; have = true; }
            mid = lo + ((hi - lo) >> 1);
            if (mid == lo) { if (!have) tau = lo; break; }
        }

        // ballot compaction
        int* ci = cidx + row * CAP;
        int base = 0;
        #pragma unroll
        for (int j = 0; j < 32; ++j) {
            uint32_t p = row32[j * 32 + lane];
            bool b0 = (p & 0xFFFFu) >= tau;
            bool b1 = (p >> 16) >= tau;
            unsigned m0 = __ballot_sync(full, b0);
            unsigned m1 = __ballot_sync(full, b1);
            if (b0) {
                int pos = base + __popc(m0 & ltmask);
                if (pos < CAP) ci[pos] = (j * 32 + lane) * 2;
            }
            base += __popc(m0);
            if (b1) {
                int pos = base + __popc(m1 & ltmask);
                if (pos < CAP) ci[pos] = (j * 32 + lane) * 2 + 1;
            }
            base += __popc(m1);
        }
        int n = base < CAP ? base : CAP;
        __syncwarp();

        // compensated fp32 re-score of candidates (reproduces fp64 ordering)
        double* cv = cval + row * CAP;
        for (int i = lane; i < n; i += 32) {
            const float4* k4 = (const float4*)(kb + (size_t)ci[i] * D_);
            const float4* q4 = (const float4*)qrow;
            float s = 0.0f, c = 0.0f;
            #pragma unroll
            for (int dg = 0; dg < D_ / 4; ++dg) {
                float4 kv = k4[dg];
                float4 qv = q4[dg];
                dot2_step(qv.x, kv.x, s, c);
                dot2_step(qv.y, kv.y, s, c);
                dot2_step(qv.z, kv.z, s, c);
                dot2_step(qv.w, kv.w, s, c);
            }
            cv[i] = ((double)s + (double)c) * 0.125;
        }
        __syncwarp();

        // parallel rank -> exact top-32 (val desc, tie -> lower index)
        int* si = sidx + row * TOPK_;
        float* sv = sval + row * TOPK_;
        for (int i = lane; i < n; i += 32) {
            double vi = cv[i];
            int    ii = ci[i];
            int rank = 0;
            for (int j = 0; j < n; ++j) {
                double vj = cv[j];
                rank += (vj > vi) || (vj == vi && ci[j] < ii);
            }
            if (rank < TOPK_) { si[rank] = ii; sv[rank] = (float)vi; }
        }
        __syncwarp();

        // output: out[grow][d] = sum_j val_j * V[idx_j][d]
        float a0 = 0.0f, a1 = 0.0f;
        #pragma unroll
        for (int j = 0; j < TOPK_; ++j) {
            float vv = sv[j];
            const float* vrow = vb + (size_t)si[j] * D_;
            a0 = fmaf(vv, vrow[lane], a0);
            a1 = fmaf(vv, vrow[lane + 32], a1);
        }
        out[(size_t)grow * D_ + lane]      = a0;
        out[(size_t)grow * D_ + lane + 32] = a1;
        __syncwarp();
    }
}

// ---------------------------------------------------------------------------
extern "C" void kernel_launch(void* const* d_in, const int* in_sizes, int n_in,
                              void* d_out, int out_size)
{
    const float* q = (const float*)d_in[0];
    const float* k = (const float*)d_in[1];
    const float* v = (const float*)d_in[2];
    float* out = (float*)d_out;

    cudaFuncSetAttribute(fused_topk_attn,
                         cudaFuncAttributeMaxDynamicSharedMemorySize, SMEM_BYTES);
    fused_topk_attn<<<NBLK, 256, SMEM_BYTES>>>(q, k, v, out);
}

// round 8
// speedup vs baseline: 1.9577x; 1.2594x over previous
#include <cuda_runtime.h>
#include <cuda_bf16.h>
#include <cstdint>

// Problem constants
#define B_    8
#define L_    2048
#define D_    64
#define TOPK_ 32

// Fused tiling
#define TQ     32                // query rows per block
#define CK     128               // keys per chunk
#define NCHUNK (L_ / CK)         // 16
#define NBLK   (B_ * L_ / TQ)    // 512
#define BPB    (L_ / TQ)         // 64

// Selection: analytic threshold tau = Z_TAU * ||q|| / 8
// count ~ Binomial(2048, P(Z>1.70)=.0446): E=91.3, sd=9.3
#define Z_TAU 1.70f
#define MINC  40                 // containment guard (P<2e-8/row)
#define CAP   144                // overflow guard  (P<1e-8/row)

#define KST  72                  // Kbf smem row stride (bf16 elems) = 144B pitch

// ---- dynamic shared memory layout (bytes) ----
#define OFF_KBF   0              // bf16 [2][128][72]   = 36864
#define OFF_CIDX  36864          // int  [32][144]      = 18432
#define OFF_CVAL  55296          // dbl  [32][144]      = 36864
#define OFF_QS    92160          // f32  [32][68]       =  8704
#define OFF_TAU   100864         // f32  [32]           =   128
#define OFF_CNT   100992         // int  [32]           =   128
#define OFF_SIDX  101120         // int  [32][32]       =  4096
#define OFF_SVAL  105216         // f32  [32][32]       =  4096
#define SMEM_BYTES 109312        // x2 blocks/SM = 218624 <= 228KB

// K pre-converted to bf16 (2 MB)
__device__ __nv_bfloat16 gKbf[(size_t)B_ * L_ * D_];

__device__ __forceinline__ unsigned f2sortable(float f) {
    unsigned bb = __float_as_uint(f);
    return (bb & 0x80000000u) ? ~bb : (bb | 0x80000000u);
}

__device__ __forceinline__ uint32_t pack_bf2(float lo, float hi) {
    __nv_bfloat162 h2 = __floats2bfloat162_rn(lo, hi);
    return *reinterpret_cast<uint32_t*>(&h2);
}

__device__ __forceinline__ void dot2_step(float a, float b, float& s, float& c) {
    float p  = __fmul_rn(a, b);
    float e  = __fmaf_rn(a, b, -p);
    float t1 = __fadd_rn(s, p);
    float bv = __fsub_rn(t1, s);
    float e2 = __fadd_rn(__fsub_rn(s, __fsub_rn(t1, bv)), __fsub_rn(p, bv));
    s = t1;
    c = __fadd_rn(c, __fadd_rn(e, e2));
}

__device__ __forceinline__ void mma_bf16(
    float& c0, float& c1, float& c2, float& c3,
    uint32_t a0, uint32_t a1, uint32_t a2, uint32_t a3,
    uint32_t b0, uint32_t b1)
{
    asm volatile(
        "mma.sync.aligned.m16n8k16.row.col.f32.bf16.bf16.f32 "
        "{%0,%1,%2,%3}, {%4,%5,%6,%7}, {%8,%9}, {%0,%1,%2,%3};\n"
        : "+f"(c0), "+f"(c1), "+f"(c2), "+f"(c3)
        : "r"(a0), "r"(a1), "r"(a2), "r"(a3), "r"(b0), "r"(b1));
}

__device__ __forceinline__ void cp_async16(uint32_t smem_dst, const void* gsrc) {
    asm volatile("cp.async.cg.shared.global [%0], [%1], 16;\n"
                 :: "r"(smem_dst), "l"(gsrc));
}
__device__ __forceinline__ void cp_commit() {
    asm volatile("cp.async.commit_group;\n");
}
template <int N>
__device__ __forceinline__ void cp_wait() {
    asm volatile("cp.async.wait_group %0;\n" :: "n"(N));
}

// fallback scorer: fp32 q x bf16 k, deterministic order
__device__ __forceinline__ float dot_qk_bf(const float* qrow, const __nv_bfloat16* krow) {
    float s = 0.0f;
    #pragma unroll
    for (int d0 = 0; d0 < D_; d0 += 2) {
        __nv_bfloat162 kk = *(const __nv_bfloat162*)(krow + d0);
        s = fmaf(qrow[d0],     __bfloat162float(kk.x), s);
        s = fmaf(qrow[d0 + 1], __bfloat162float(kk.y), s);
    }
    return s * 0.125f;
}

// ---------------------------------------------------------------------------
// Kernel 0: K fp32 -> bf16
// ---------------------------------------------------------------------------
__global__ __launch_bounds__(256) void convert_k(const float* __restrict__ k) {
    int idx = blockIdx.x * 256 + threadIdx.x;         // 262144 float4 segs
    float4 kv = *(const float4*)(k + (size_t)idx * 4);
    uint2 o;
    o.x = pack_bf2(kv.x, kv.y);
    o.y = pack_bf2(kv.z, kv.w);
    *(uint2*)((unsigned short*)gKbf + (size_t)idx * 4) = o;
}

// ---------------------------------------------------------------------------
// Kernel 1: fused score + select + output. 2 blocks/SM.
// ---------------------------------------------------------------------------
__global__ __launch_bounds__(256, 2) void fused_topk_attn(
    const float* __restrict__ q, const float* __restrict__ k,
    const float* __restrict__ v, float* __restrict__ out)
{
    extern __shared__ __align__(16) char smem[];
    unsigned short* Kbf = (unsigned short*)(smem + OFF_KBF);
    int*    cidx = (int*)(smem + OFF_CIDX);
    double* cval = (double*)(smem + OFF_CVAL);
    float*  Qs   = (float*)(smem + OFF_QS);
    float*  tauA = (float*)(smem + OFF_TAU);
    int*    cnt  = (int*)(smem + OFF_CNT);
    int*    sidx = (int*)(smem + OFF_SIDX);
    float*  sval = (float*)(smem + OFF_SVAL);

    const int t    = threadIdx.x;
    const int lane = t & 31;
    const int w    = t >> 5;
    const unsigned full = 0xffffffffu;
    const unsigned ltmask = (1u << lane) - 1u;

    const int rowBase = blockIdx.x * TQ;
    const int b       = blockIdx.x / BPB;
    const float* kb   = k + (size_t)b * L_ * D_;
    const float* vb   = v + (size_t)b * L_ * D_;
    const __nv_bfloat16* gkb = gKbf + (size_t)b * L_ * D_;

    const uint32_t ksBase = (uint32_t)__cvta_generic_to_shared(Kbf);

    // ---- stage Q fp32; zero counters ----
    for (int i = t; i < TQ * 16; i += 256) {
        int row = i >> 4, dg4 = (i & 15) << 2;
        *(float4*)(Qs + row * 68 + dg4) =
            *(const float4*)(q + ((size_t)(rowBase + row)) * D_ + dg4);
    }
    if (t < TQ) cnt[t] = 0;
    __syncthreads();

    // ---- per-row analytic tau (warp w -> rows 4w..4w+3) ----
    for (int rr = 0; rr < 4; ++rr) {
        int row = w * 4 + rr;
        float x = Qs[row * 68 + lane], y = Qs[row * 68 + lane + 32];
        float nrm = x * x + y * y;
        #pragma unroll
        for (int o = 16; o >= 1; o >>= 1) nrm += __shfl_xor_sync(full, nrm, o);
        if (lane == 0) tauA[row] = Z_TAU * sqrtf(nrm) * 0.125f;
    }

    // ---- A fragments from Qs (bf16 pairs), loaded once ----
    const int rg = w >> 2;                 // row-group (0/1)
    const int ns = w & 3;                  // 32-key slice
    const int ar = rg * 16 + (lane >> 2);
    const int ac = (lane & 3) * 2;
    uint32_t afr[4][4];
    #pragma unroll
    for (int ks = 0; ks < 4; ++ks) {
        int col = ks * 16 + ac;
        afr[ks][0] = pack_bf2(Qs[ar * 68 + col],       Qs[ar * 68 + col + 1]);
        afr[ks][1] = pack_bf2(Qs[(ar + 8) * 68 + col], Qs[(ar + 8) * 68 + col + 1]);
        afr[ks][2] = pack_bf2(Qs[ar * 68 + col + 8],   Qs[ar * 68 + col + 9]);
        afr[ks][3] = pack_bf2(Qs[(ar + 8) * 68 + col + 8], Qs[(ar + 8) * 68 + col + 9]);
    }

    // ---- prologue: cp.async chunk 0 (bf16 K) ----
    #pragma unroll
    for (int g = 0; g < 4; ++g) {
        int seg = g * 256 + t;             // 1024 x 16B = 16KB
        int key = seg >> 3, o = seg & 7;
        cp_async16(ksBase + (uint32_t)(key * 144 + o * 16),
                   gkb + (size_t)key * D_ + o * 8);
    }
    cp_commit();
    __syncthreads();                        // tau visible before epilogue

    // ---- mainloop: HMMA + threshold epilogue ----
    for (int chunk = 0; chunk < NCHUNK; ++chunk) {
        if (chunk + 1 < NCHUNK) {
            const int keyNext = (chunk + 1) * CK;
            const uint32_t dstB = ksBase + ((chunk + 1) & 1) * 18432;
            #pragma unroll
            for (int g = 0; g < 4; ++g) {
                int seg = g * 256 + t;
                int key = seg >> 3, o = seg & 7;
                cp_async16(dstB + (uint32_t)(key * 144 + o * 16),
                           gkb + (size_t)(keyNext + key) * D_ + o * 8);
            }
            cp_commit();
            cp_wait<1>();
        } else {
            cp_wait<0>();
        }
        __syncthreads();

        const unsigned short* Kb = Kbf + (chunk & 1) * (CK * KST);
        const float tau_a = tauA[ar], tau_b = tauA[ar + 8];
        #pragma unroll
        for (int nt = 0; nt < 4; ++nt) {
            const int keyInChunk = ns * 32 + nt * 8 + (lane >> 2);
            float c0 = 0.f, c1 = 0.f, c2 = 0.f, c3 = 0.f;
            #pragma unroll
            for (int ks = 0; ks < 4; ++ks) {
                int col = ks * 16 + ac;
                uint32_t b0 = *(const uint32_t*)&Kb[keyInChunk * KST + col];
                uint32_t b1 = *(const uint32_t*)&Kb[keyInChunk * KST + col + 8];
                mma_bf16(c0, c1, c2, c3,
                         afr[ks][0], afr[ks][1], afr[ks][2], afr[ks][3], b0, b1);
            }
            const int kcol = chunk * CK + ns * 32 + nt * 8 + ac;
            c0 *= 0.125f; c1 *= 0.125f; c2 *= 0.125f; c3 *= 0.125f;
            if (c0 >= tau_a) { int p = atomicAdd(&cnt[ar], 1);     if (p < CAP) cidx[ar * CAP + p] = kcol; }
            if (c1 >= tau_a) { int p = atomicAdd(&cnt[ar], 1);     if (p < CAP) cidx[ar * CAP + p] = kcol + 1; }
            if (c2 >= tau_b) { int p = atomicAdd(&cnt[ar + 8], 1); if (p < CAP) cidx[(ar + 8) * CAP + p] = kcol; }
            if (c3 >= tau_b) { int p = atomicAdd(&cnt[ar + 8], 1); if (p < CAP) cidx[(ar + 8) * CAP + p] = kcol + 1; }
        }
        __syncthreads();
    }

    // ---- selection: warp w rows 4w..4w+3 ----
    for (int rr = 0; rr < 4; ++rr) {
        const int row  = w * 4 + rr;
        const int grow = rowBase + row;
        const float* qrow = Qs + row * 68;
        int* ci = cidx + row * CAP;
        int n = cnt[row];

        if (n < MINC || n > CAP) {
            // ---- rare fallback: warp-local bisection over recomputed scores ----
            unsigned lo = 0u, hi = 0xFFFFFFFFu, mid = f2sortable(tauA[row]), tu = 0u;
            bool have = false;
            for (int it = 0; it < 34; ++it) {
                int c = 0;
                for (int j = 0; j < 64; ++j) {
                    float s = dot_qk_bf(qrow, gkb + (size_t)(j * 32 + lane) * D_);
                    c += (f2sortable(s) >= mid);
                }
                #pragma unroll
                for (int o = 16; o >= 1; o >>= 1) c += __shfl_xor_sync(full, c, o);
                if (c >= MINC && c <= CAP) { tu = mid; have = true; break; }
                if (c < MINC) hi = mid; else { lo = mid; tu = mid; have = true; }
                mid = lo + ((hi - lo) >> 1);
                if (mid == lo) { if (!have) tu = lo; break; }
            }
            int base = 0;
            for (int j = 0; j < 64; ++j) {
                int key = j * 32 + lane;
                float s = dot_qk_bf(qrow, gkb + (size_t)key * D_);
                bool cnd = f2sortable(s) >= tu;
                unsigned m = __ballot_sync(full, cnd);
                if (cnd) {
                    int pos = base + __popc(m & ltmask);
                    if (pos < CAP) ci[pos] = key;
                }
                base += __popc(m);
            }
            n = base < CAP ? base : CAP;
        }
        __syncwarp();

        // compensated fp32 re-score (reproduces fp64 ordering)
        double* cv = cval + row * CAP;
        for (int i = lane; i < n; i += 32) {
            const float4* k4 = (const float4*)(kb + (size_t)ci[i] * D_);
            const float4* q4 = (const float4*)qrow;
            float s = 0.0f, c = 0.0f;
            #pragma unroll
            for (int dg = 0; dg < D_ / 4; ++dg) {
                float4 kv = k4[dg];
                float4 qv = q4[dg];
                dot2_step(qv.x, kv.x, s, c);
                dot2_step(qv.y, kv.y, s, c);
                dot2_step(qv.z, kv.z, s, c);
                dot2_step(qv.w, kv.w, s, c);
            }
            cv[i] = ((double)s + (double)c) * 0.125;
        }
        __syncwarp();

        // parallel rank -> exact top-32 (val desc, tie -> lower index)
        int* si = sidx + row * TOPK_;
        float* sv = sval + row * TOPK_;
        for (int i = lane; i < n; i += 32) {
            double vi = cv[i];
            int    ii = ci[i];
            int rank = 0;
            for (int j = 0; j < n; ++j) {
                double vj = cv[j];
                rank += (vj > vi) || (vj == vi && ci[j] < ii);
            }
            if (rank < TOPK_) { si[rank] = ii; sv[rank] = (float)vi; }
        }
        __syncwarp();

        // output
        float a0 = 0.0f, a1 = 0.0f;
        #pragma unroll
        for (int j = 0; j < TOPK_; ++j) {
            float vv = sv[j];
            const float* vrow = vb + (size_t)si[j] * D_;
            a0 = fmaf(vv, vrow[lane], a0);
            a1 = fmaf(vv, vrow[lane + 32], a1);
        }
        out[(size_t)grow * D_ + lane]      = a0;
        out[(size_t)grow * D_ + lane + 32] = a1;
        __syncwarp();
    }
}

// ---------------------------------------------------------------------------
extern "C" void kernel_launch(void* const* d_in, const int* in_sizes, int n_in,
                              void* d_out, int out_size)
{
    const float* q = (const float*)d_in[0];
    const float* k = (const float*)d_in[1];
    const float* v = (const float*)d_in[2];
    float* out = (float*)d_out;

    convert_k<<<(B_ * L_ * D_ / 4) / 256, 256>>>(k);

    cudaFuncSetAttribute(fused_topk_attn,
                         cudaFuncAttributeMaxDynamicSharedMemorySize, SMEM_BYTES);
    fused_topk_attn<<<NBLK, 256, SMEM_BYTES>>>(q, k, v, out);
}

// round 9
// speedup vs baseline: 3.4621x; 1.7684x over previous
#include <cuda_runtime.h>
#include <cuda_bf16.h>
#include <cstdint>

// Problem constants
#define B_    8
#define L_    2048
#define D_    64
#define TOPK_ 32

// Kernel A tiling
#define TQ     32                // query rows per block
#define CK     128               // keys per chunk
#define NCHUNK (L_ / CK)         // 16
#define NBLK   (B_ * L_ / TQ)    // 512
#define BPB    (L_ / TQ)         // 64

// Selection: analytic threshold tau = Z_TAU * ||q|| / 8
// count ~ Binomial(2048, P(Z>1.70)=.0446): E=91.3, sd=9.3
#define Z_TAU 1.70f
#define MINC  40                 // containment guard (P<2e-8/row)
#define CAP   144                // overflow guard  (P<1e-8/row)
#define CAPG  160                // global candidate stride

#define KST  72                  // Kbf smem row stride (bf16 elems)

// ---- kernel A dynamic smem layout (bytes), 45824 total ----
#define OFF_KBF   0              // bf16 [2][128][72] = 36864
#define OFF_QS    36864          // f32  [32][68]     =  8704
#define OFF_TAU   45568          // f32  [32]
#define OFF_CNT   45696          // int  [32]
#define SMEM_A    45824

// Global scratch
__device__ __nv_bfloat16 gKbf[(size_t)B_ * L_ * D_];      // 2 MB
__device__ int g_cnt[B_ * L_];
__device__ int g_cand[(size_t)B_ * L_ * CAPG];            // 10.5 MB

__device__ __forceinline__ unsigned f2sortable(float f) {
    unsigned bb = __float_as_uint(f);
    return (bb & 0x80000000u) ? ~bb : (bb | 0x80000000u);
}

__device__ __forceinline__ uint32_t pack_bf2(float lo, float hi) {
    __nv_bfloat162 h2 = __floats2bfloat162_rn(lo, hi);
    return *reinterpret_cast<uint32_t*>(&h2);
}

__device__ __forceinline__ void mma_bf16(
    float& c0, float& c1, float& c2, float& c3,
    uint32_t a0, uint32_t a1, uint32_t a2, uint32_t a3,
    uint32_t b0, uint32_t b1)
{
    asm volatile(
        "mma.sync.aligned.m16n8k16.row.col.f32.bf16.bf16.f32 "
        "{%0,%1,%2,%3}, {%4,%5,%6,%7}, {%8,%9}, {%0,%1,%2,%3};\n"
        : "+f"(c0), "+f"(c1), "+f"(c2), "+f"(c3)
        : "r"(a0), "r"(a1), "r"(a2), "r"(a3), "r"(b0), "r"(b1));
}

__device__ __forceinline__ void cp_async16(uint32_t smem_dst, const void* gsrc) {
    asm volatile("cp.async.cg.shared.global [%0], [%1], 16;\n"
                 :: "r"(smem_dst), "l"(gsrc));
}
__device__ __forceinline__ void cp_commit() {
    asm volatile("cp.async.commit_group;\n");
}
template <int N>
__device__ __forceinline__ void cp_wait() {
    asm volatile("cp.async.wait_group %0;\n" :: "n"(N));
}

// ---------------------------------------------------------------------------
// Kernel 0: K fp32 -> bf16
// ---------------------------------------------------------------------------
__global__ __launch_bounds__(256) void convert_k(const float* __restrict__ k) {
    int idx = blockIdx.x * 256 + threadIdx.x;
    float4 kv = *(const float4*)(k + (size_t)idx * 4);
    uint2 o;
    o.x = pack_bf2(kv.x, kv.y);
    o.y = pack_bf2(kv.z, kv.w);
    *(uint2*)((unsigned short*)gKbf + (size_t)idx * 4) = o;
}

// ---------------------------------------------------------------------------
// Kernel A: HMMA scores + analytic-threshold candidate harvest -> global
// ---------------------------------------------------------------------------
__global__ __launch_bounds__(256, 3) void score_harvest(
    const float* __restrict__ q)
{
    extern __shared__ __align__(16) char smem[];
    unsigned short* Kbf = (unsigned short*)(smem + OFF_KBF);
    float* Qs   = (float*)(smem + OFF_QS);
    float* tauA = (float*)(smem + OFF_TAU);
    int*   cnt  = (int*)(smem + OFF_CNT);

    const int t    = threadIdx.x;
    const int lane = t & 31;
    const int w    = t >> 5;
    const unsigned full = 0xffffffffu;

    const int rowBase = blockIdx.x * TQ;
    const int b       = blockIdx.x / BPB;
    const __nv_bfloat16* gkb = gKbf + (size_t)b * L_ * D_;
    const uint32_t ksBase = (uint32_t)__cvta_generic_to_shared(Kbf);

    for (int i = t; i < TQ * 16; i += 256) {
        int row = i >> 4, dg4 = (i & 15) << 2;
        *(float4*)(Qs + row * 68 + dg4) =
            *(const float4*)(q + ((size_t)(rowBase + row)) * D_ + dg4);
    }
    if (t < TQ) cnt[t] = 0;
    __syncthreads();

    // per-row analytic tau (warp w -> rows 4w..4w+3)
    for (int rr = 0; rr < 4; ++rr) {
        int row = w * 4 + rr;
        float x = Qs[row * 68 + lane], y = Qs[row * 68 + lane + 32];
        float nrm = x * x + y * y;
        #pragma unroll
        for (int o = 16; o >= 1; o >>= 1) nrm += __shfl_xor_sync(full, nrm, o);
        if (lane == 0) tauA[row] = Z_TAU * sqrtf(nrm) * 0.125f;
    }

    // A fragments (Q) once
    const int rg = w >> 2;
    const int ns = w & 3;
    const int ar = rg * 16 + (lane >> 2);
    const int ac = (lane & 3) * 2;
    uint32_t afr[4][4];
    #pragma unroll
    for (int ks = 0; ks < 4; ++ks) {
        int col = ks * 16 + ac;
        afr[ks][0] = pack_bf2(Qs[ar * 68 + col],           Qs[ar * 68 + col + 1]);
        afr[ks][1] = pack_bf2(Qs[(ar + 8) * 68 + col],     Qs[(ar + 8) * 68 + col + 1]);
        afr[ks][2] = pack_bf2(Qs[ar * 68 + col + 8],       Qs[ar * 68 + col + 9]);
        afr[ks][3] = pack_bf2(Qs[(ar + 8) * 68 + col + 8], Qs[(ar + 8) * 68 + col + 9]);
    }

    // prologue chunk 0
    #pragma unroll
    for (int g = 0; g < 4; ++g) {
        int seg = g * 256 + t;
        int key = seg >> 3, o = seg & 7;
        cp_async16(ksBase + (uint32_t)(key * 144 + o * 16),
                   gkb + (size_t)key * D_ + o * 8);
    }
    cp_commit();
    __syncthreads();                       // tau + cnt visible

    int* candRowA = g_cand + (size_t)(rowBase + ar) * CAPG;
    int* candRowB = g_cand + (size_t)(rowBase + ar + 8) * CAPG;

    for (int chunk = 0; chunk < NCHUNK; ++chunk) {
        if (chunk + 1 < NCHUNK) {
            const int keyNext = (chunk + 1) * CK;
            const uint32_t dstB = ksBase + ((chunk + 1) & 1) * 18432;
            #pragma unroll
            for (int g = 0; g < 4; ++g) {
                int seg = g * 256 + t;
                int key = seg >> 3, o = seg & 7;
                cp_async16(dstB + (uint32_t)(key * 144 + o * 16),
                           gkb + (size_t)(keyNext + key) * D_ + o * 8);
            }
            cp_commit();
            cp_wait<1>();
        } else {
            cp_wait<0>();
        }
        __syncthreads();

        const unsigned short* Kb = Kbf + (chunk & 1) * (CK * KST);
        const float tau_a = tauA[ar], tau_b = tauA[ar + 8];
        #pragma unroll
        for (int nt = 0; nt < 4; ++nt) {
            const int keyInChunk = ns * 32 + nt * 8 + (lane >> 2);
            float c0 = 0.f, c1 = 0.f, c2 = 0.f, c3 = 0.f;
            #pragma unroll
            for (int ks = 0; ks < 4; ++ks) {
                int col = ks * 16 + ac;
                uint32_t b0 = *(const uint32_t*)&Kb[keyInChunk * KST + col];
                uint32_t b1 = *(const uint32_t*)&Kb[keyInChunk * KST + col + 8];
                mma_bf16(c0, c1, c2, c3,
                         afr[ks][0], afr[ks][1], afr[ks][2], afr[ks][3], b0, b1);
            }
            const int kcol = chunk * CK + ns * 32 + nt * 8 + ac;
            c0 *= 0.125f; c1 *= 0.125f; c2 *= 0.125f; c3 *= 0.125f;
            if (c0 >= tau_a) { int p = atomicAdd(&cnt[ar], 1);     if (p < CAP) candRowA[p] = kcol; }
            if (c1 >= tau_a) { int p = atomicAdd(&cnt[ar], 1);     if (p < CAP) candRowA[p] = kcol + 1; }
            if (c2 >= tau_b) { int p = atomicAdd(&cnt[ar + 8], 1); if (p < CAP) candRowB[p] = kcol; }
            if (c3 >= tau_b) { int p = atomicAdd(&cnt[ar + 8], 1); if (p < CAP) candRowB[p] = kcol + 1; }
        }
        __syncthreads();
    }

    if (t < TQ) g_cnt[rowBase + t] = cnt[t];
}

// ---------------------------------------------------------------------------
// Kernel B: one warp per query row — fp32 rescore, u64-key exact top-32, output
// ---------------------------------------------------------------------------
__global__ __launch_bounds__(256) void select_rows(
    const float* __restrict__ q, const float* __restrict__ k,
    const float* __restrict__ v, float* __restrict__ out)
{
    __shared__ unsigned long long keys[8][CAP];
    __shared__ float qs[8][64];
    __shared__ float selv[8][TOPK_];
    __shared__ int   seli[8][TOPK_];

    const int t    = threadIdx.x;
    const int lane = t & 31;
    const int w    = t >> 5;
    const unsigned full = 0xffffffffu;
    const unsigned ltmask = (1u << lane) - 1u;

    const int r = blockIdx.x * 8 + w;
    const int b = r >> 11;
    const float* kb = k + (size_t)b * L_ * D_;
    const float* vb = v + (size_t)b * L_ * D_;

    qs[w][lane]      = q[(size_t)r * D_ + lane];
    qs[w][lane + 32] = q[(size_t)r * D_ + lane + 32];
    __syncwarp();

    int n = g_cnt[r];
    const bool fb = (n < MINC || n > CAP);

    if (fb) {
        // rare fallback: fp32 bisection threshold + ballot compaction
        float nrm = qs[w][lane] * qs[w][lane] + qs[w][lane + 32] * qs[w][lane + 32];
        #pragma unroll
        for (int o = 16; o >= 1; o >>= 1) nrm += __shfl_xor_sync(full, nrm, o);
        unsigned lo = 0u, hi = 0xFFFFFFFFu;
        unsigned mid = f2sortable(Z_TAU * sqrtf(nrm) * 0.125f), tu = 0u;
        bool have = false;
        for (int it = 0; it < 34; ++it) {
            int c = 0;
            for (int j = 0; j < 64; ++j) {
                const float4* k4 = (const float4*)(kb + (size_t)(j * 32 + lane) * D_);
                float s = 0.0f;
                #pragma unroll
                for (int dg = 0; dg < 16; ++dg) {
                    float4 kv = k4[dg];
                    const float* qq = &qs[w][dg * 4];
                    s = fmaf(qq[0], kv.x, s); s = fmaf(qq[1], kv.y, s);
                    s = fmaf(qq[2], kv.z, s); s = fmaf(qq[3], kv.w, s);
                }
                c += (f2sortable(s * 0.125f) >= mid);
            }
            #pragma unroll
            for (int o = 16; o >= 1; o >>= 1) c += __shfl_xor_sync(full, c, o);
            if (c >= MINC && c <= CAP) { tu = mid; have = true; break; }
            if (c < MINC) hi = mid; else { lo = mid; tu = mid; have = true; }
            mid = lo + ((hi - lo) >> 1);
            if (mid == lo) { if (!have) tu = lo; break; }
        }
        int base = 0;
        for (int j = 0; j < 64; ++j) {
            int key = j * 32 + lane;
            const float4* k4 = (const float4*)(kb + (size_t)key * D_);
            float s = 0.0f;
            #pragma unroll
            for (int dg = 0; dg < 16; ++dg) {
                float4 kv = k4[dg];
                const float* qq = &qs[w][dg * 4];
                s = fmaf(qq[0], kv.x, s); s = fmaf(qq[1], kv.y, s);
                s = fmaf(qq[2], kv.z, s); s = fmaf(qq[3], kv.w, s);
            }
            bool cnd = f2sortable(s * 0.125f) >= tu;
            unsigned m = __ballot_sync(full, cnd);
            if (cnd) {
                int pos = base + __popc(m & ltmask);
                if (pos < CAP) keys[w][pos] = (unsigned long long)key;  // stage idx
            }
            base += __popc(m);
        }
        n = base < CAP ? base : CAP;
        __syncwarp();
    }

    // gather my candidates (i = lane + 32j slots; same-lane read/write of keys)
    int   midx[5];
    float mval[5];
    unsigned long long mkey[5] = {0ull, 0ull, 0ull, 0ull, 0ull}; // 0 = sentinel (rank >= n)
    int mc = 0;
    const int* candRow = g_cand + (size_t)r * CAPG;
    for (int i = lane; i < n; i += 32) {
        int idx = fb ? (int)keys[w][i] : candRow[i];
        const float4* k4 = (const float4*)(kb + (size_t)idx * D_);
        float s = 0.0f;
        #pragma unroll
        for (int dg = 0; dg < 16; ++dg) {
            float4 kv = k4[dg];
            const float* qq = &qs[w][dg * 4];
            s = fmaf(qq[0], kv.x, s); s = fmaf(qq[1], kv.y, s);
            s = fmaf(qq[2], kv.z, s); s = fmaf(qq[3], kv.w, s);
        }
        s *= 0.125f;
        unsigned long long key =
            ((unsigned long long)f2sortable(s) << 32) | (unsigned)(2047 - idx);
        keys[w][i] = key;
        midx[mc] = idx; mval[mc] = s; mkey[mc] = key; ++mc;
    }
    __syncwarp();

    // exact top-32 by rank (u64 compares: val desc, tie -> lower idx)
    int rk[5] = {0, 0, 0, 0, 0};
    for (int j = 0; j < n; ++j) {
        unsigned long long kj = keys[w][j];
        #pragma unroll
        for (int c = 0; c < 5; ++c) rk[c] += (kj > mkey[c]);
    }
    #pragma unroll
    for (int c = 0; c < 5; ++c)
        if (c < mc && rk[c] < TOPK_) { selv[w][rk[c]] = mval[c]; seli[w][rk[c]] = midx[c]; }
    __syncwarp();

    // output
    float a0 = 0.0f, a1 = 0.0f;
    #pragma unroll
    for (int j = 0; j < TOPK_; ++j) {
        float vv = selv[w][j];
        const float* vrow = vb + (size_t)seli[w][j] * D_;
        a0 = fmaf(vv, vrow[lane], a0);
        a1 = fmaf(vv, vrow[lane + 32], a1);
    }
    out[(size_t)r * D_ + lane]      = a0;
    out[(size_t)r * D_ + lane + 32] = a1;
}

// ---------------------------------------------------------------------------
extern "C" void kernel_launch(void* const* d_in, const int* in_sizes, int n_in,
                              void* d_out, int out_size)
{
    const float* q = (const float*)d_in[0];
    const float* k = (const float*)d_in[1];
    const float* v = (const float*)d_in[2];
    float* out = (float*)d_out;

    convert_k<<<(B_ * L_ * D_ / 4) / 256, 256>>>(k);

    cudaFuncSetAttribute(score_harvest,
                         cudaFuncAttributeMaxDynamicSharedMemorySize, SMEM_A);
    score_harvest<<<NBLK, 256, SMEM_A>>>(q);

    select_rows<<<B_ * L_ / 8, 256>>>(q, k, v, out);
}